// round 2
// baseline (speedup 1.0000x reference)
#include <cuda_runtime.h>
#include <cstdint>
#include <cstddef>

// ---------------------------------------------------------------------------
// sMGU cell: B=65536, IN=256, H=512
// Fused tf32 mma.sync GEMM  [B,768] @ [768,1024]  (weights pre-transposed,
// f/c gates interleaved per column pair) + fused elementwise epilogue.
// Base-target features only (cp.async + mma.sync tf32) — the harness build
// goes through compute_103 (no 'a'), so tcgen05 is unavailable.
// ---------------------------------------------------------------------------

#define H_DIM   512
#define BH      33554432ull            // B*H
#define KTOT    768
#define KC      32                     // k-chunk (floats)
#define NCHUNK  24                     // 768/32
#define ROWF    36                     // smem row stride in floats (pad 32->36)
#define TILE_W  (128 * ROWF)           // words per tile (A or B)
#define SMEM_BYTES (2 * 2 * TILE_W * 4)  // 2 stages x (A+B) = 73728 B

// Wt[n][k], n in [0,1024): h = n>>1, gate = n&1 (0=f, 1=c). tf32-rounded (RN).
__device__ float g_Wt[1024 * KTOT];

// ------------------------------- helpers -----------------------------------
__device__ __forceinline__ uint32_t smem_u32(const void* p) {
    uint32_t a;
    asm("{ .reg .u64 t; cvta.to.shared.u64 t, %1; cvt.u32.u64 %0, t; }"
        : "=r"(a) : "l"(p));
    return a;
}
__device__ __forceinline__ void cp16(uint32_t dst, const void* src) {
    asm volatile("cp.async.cg.shared.global [%0], [%1], 16;"
                 :: "r"(dst), "l"(src));
}
__device__ __forceinline__ float tf32rn(float v) {
    asm("cvt.rna.tf32.f32 %0, %0;" : "+f"(v));
    return v;
}
__device__ __forceinline__ void mma_tf32(float* d, const uint32_t* a,
                                         const uint32_t* b) {
    asm volatile(
        "mma.sync.aligned.m16n8k8.row.col.f32.tf32.tf32.f32 "
        "{%0,%1,%2,%3}, {%4,%5,%6,%7}, {%8,%9}, {%0,%1,%2,%3};"
        : "+f"(d[0]), "+f"(d[1]), "+f"(d[2]), "+f"(d[3])
        : "r"(a[0]), "r"(a[1]), "r"(a[2]), "r"(a[3]), "r"(b[0]), "r"(b[1]));
}

__device__ __forceinline__ float tanh_fast(float v) {
    float e = __expf(2.0f * v);
    return 1.0f - __fdividef(2.0f, e + 1.0f);
}
__device__ __forceinline__ void cell(float df, float dc, float bfe, float bce,
                                     float mpv, float cpv, float npv,
                                     float& h, float& c, float& n, float& m) {
    float a  = df + bfe + mpv;              // log f_t + m_prev
    m = fmaxf(a, 0.0f);
    float e  = __expf(-fabsf(a));           // single exp covers both branches
    float fp = (a >= 0.0f) ? 1.0f : e;      // exp(a - m)
    float ip = (a >= 0.0f) ? e : 1.0f;      // exp(-m)
    float th = tanh_fast(dc + bce);
    c = fp * cpv + ip * th;
    n = fp * npv + ip;
    h = tanh_fast(__fdividef(c, fmaxf(n, 1e-8f)));
}

// ------------------------------ prep kernel --------------------------------
__global__ void prep_weights(const float* __restrict__ wf,
                             const float* __restrict__ wc,
                             const float* __restrict__ rf,
                             const float* __restrict__ rc) {
    int n = blockIdx.x;                 // 0..1023
    int h = n >> 1, gate = n & 1;
    const float* W = gate ? wc : wf;
    const float* R = gate ? rc : rf;
    for (int k = threadIdx.x; k < KTOT; k += blockDim.x) {
        float v = (k < 256) ? W[(size_t)k * H_DIM + h]
                            : R[(size_t)(k - 256) * H_DIM + h];
        g_Wt[(size_t)n * KTOT + k] = tf32rn(v);
    }
}

// ------------------------------ main kernel --------------------------------
// CTA 128 rows x 128 cols. 8 warps, grid (wm 0..1) x (wn 0..3), warp 64x32.
extern "C" __global__ void __launch_bounds__(256, 2)
smgu_main(const float* __restrict__ x,     const float* __restrict__ hprev,
          const float* __restrict__ cprev, const float* __restrict__ nprev,
          const float* __restrict__ mprev, const float* __restrict__ bfv,
          const float* __restrict__ bcv,   float* __restrict__ out) {
    extern __shared__ float smem[];
    const int tid  = threadIdx.x;
    const int lane = tid & 31, wid = tid >> 5;
    const int wm   = wid & 1,  wn  = wid >> 1;
    const int mtile = (int)blockIdx.x >> 3;
    const int ntile = (int)blockIdx.x & 7;
    const int m0  = mtile * 128;
    const int ncb = ntile * 128;

    const uint32_t sbase = smem_u32(smem);

    float acc[4][4][4];
#pragma unroll
    for (int i = 0; i < 4; i++)
#pragma unroll
        for (int j = 0; j < 4; j++)
#pragma unroll
            for (int r = 0; r < 4; r++) acc[i][j][r] = 0.0f;

    // ---- async loader: chunk c -> stage s -------------------------------
    auto load = [&](int c, int s) {
        const uint32_t abase = sbase + (uint32_t)(s * 2 * TILE_W) * 4u;
        const uint32_t bbase = abase + (uint32_t)TILE_W * 4u;
        const float* asrc; int astr;
        if (c < 8) { asrc = x + c * KC;            astr = 256; }
        else       { asrc = hprev + (c - 8) * KC;  astr = 512; }
#pragma unroll
        for (int u = 0; u < 4; u++) {              // A: 128 rows x 8 segs
            int i = tid + u * 256;
            int row = i >> 3, seg = i & 7;
            cp16(abase + (uint32_t)(row * (ROWF * 4) + seg * 16),
                 asrc + (size_t)(m0 + row) * astr + seg * 4);
        }
        const float* bsrc = g_Wt + (size_t)ncb * KTOT + c * KC;
#pragma unroll
        for (int u = 0; u < 4; u++) {              // B: 128 rows x 8 segs
            int i = tid + u * 256;
            int row = i >> 3, seg = i & 7;
            cp16(bbase + (uint32_t)(row * (ROWF * 4) + seg * 16),
                 bsrc + (size_t)row * KTOT + seg * 4);
        }
        asm volatile("cp.async.commit_group;" ::: "memory");
    };

    load(0, 0);
    load(1, 1);

    for (int c = 0; c < NCHUNK; c++) {
        const int s = c & 1;
        if (c < NCHUNK - 1) asm volatile("cp.async.wait_group 1;" ::: "memory");
        else                asm volatile("cp.async.wait_group 0;" ::: "memory");
        __syncthreads();

        const float* sA = smem + s * 2 * TILE_W;
        const float* sB = sA + TILE_W;

#pragma unroll
        for (int kk8 = 0; kk8 < 4; kk8++) {
            const int kk = kk8 * 8;
            uint32_t afr[4][4], bfr[4][2];
#pragma unroll
            for (int mf = 0; mf < 4; mf++) {
                const float* pa = sA + (wm * 64 + mf * 16 + (lane >> 2)) * ROWF
                                     + kk + (lane & 3);
                afr[mf][0] = __float_as_uint(tf32rn(pa[0]));
                afr[mf][1] = __float_as_uint(tf32rn(pa[8 * ROWF]));
                afr[mf][2] = __float_as_uint(tf32rn(pa[4]));
                afr[mf][3] = __float_as_uint(tf32rn(pa[8 * ROWF + 4]));
            }
#pragma unroll
            for (int nf = 0; nf < 4; nf++) {
                const float* pb = sB + (wn * 32 + nf * 8 + (lane >> 2)) * ROWF
                                     + kk + (lane & 3);
                bfr[nf][0] = __float_as_uint(pb[0]);
                bfr[nf][1] = __float_as_uint(pb[4]);
            }
#pragma unroll
            for (int mf = 0; mf < 4; mf++)
#pragma unroll
                for (int nf = 0; nf < 4; nf++)
                    mma_tf32(acc[mf][nf], afr[mf], bfr[nf]);
        }
        __syncthreads();
        if (c + 2 < NCHUNK) load(c + 2, s);
    }

    // ------------------------------ epilogue -----------------------------
    // accum fragment: c0=(row, col_f), c1=(row, col_c), c2/c3 at row+8.
    float* out_h = out;
    float* out_c = out + BH;
    float* out_n = out + 2 * BH;
    float* out_m = out + 3 * BH;

#pragma unroll
    for (int nf = 0; nf < 4; nf++) {
        const int col = ncb + wn * 32 + nf * 8 + 2 * (lane & 3);  // even
        const int hg  = col >> 1;
        const float bfe = bfv[hg];
        const float bce = bcv[hg];
#pragma unroll
        for (int mf = 0; mf < 4; mf++) {
            const int rbase = m0 + wm * 64 + mf * 16 + (lane >> 2);
#pragma unroll
            for (int hf = 0; hf < 2; hf++) {
                const size_t idx = (size_t)(rbase + hf * 8) * H_DIM + hg;
                float rh, rc, rn, rm;
                cell(acc[mf][nf][hf * 2], acc[mf][nf][hf * 2 + 1],
                     bfe, bce, mprev[idx], cprev[idx], nprev[idx],
                     rh, rc, rn, rm);
                out_h[idx] = rh;
                out_c[idx] = rc;
                out_n[idx] = rn;
                out_m[idx] = rm;
            }
        }
    }
}

// ------------------------------ launcher -----------------------------------
extern "C" void kernel_launch(void* const* d_in, const int* in_sizes, int n_in,
                              void* d_out, int out_size) {
    const float* x     = (const float*)d_in[0];
    const float* hprev = (const float*)d_in[1];
    const float* cprev = (const float*)d_in[2];
    const float* nprev = (const float*)d_in[3];
    const float* mprev = (const float*)d_in[4];
    const float* wf    = (const float*)d_in[5];
    const float* wc    = (const float*)d_in[6];
    const float* rf    = (const float*)d_in[7];
    const float* rc    = (const float*)d_in[8];
    const float* bf    = (const float*)d_in[9];
    const float* bc    = (const float*)d_in[10];

    cudaFuncSetAttribute(smgu_main,
                         cudaFuncAttributeMaxDynamicSharedMemorySize,
                         SMEM_BYTES);

    prep_weights<<<1024, 256>>>(wf, wc, rf, rc);
    smgu_main<<<4096, 256, SMEM_BYTES>>>(x, hprev, cprev, nprev, mprev,
                                         bf, bc, (float*)d_out);
}